// round 17
// baseline (speedup 1.0000x reference)
#include <cuda_runtime.h>
#include <cuda_fp16.h>
#include <cstdint>

#define BB 4
#define TT 4096
#define CC 512
#define HH 64
#define LOG2E 1.4426950408889634f
#define SCALE 0.044194173824159216f   // 512^-0.5
#define CH 16                          // k-tiles (64 keys) per split-K chunk

// fp16 operands
__device__ __half g_qh[BB * TT * HH];      // q * SCALE * log2e, [tok][h]
__device__ __half g_kh[BB * TT * HH];      // k, [tok][h]
__device__ __half g_vt[BB * HH * TT];      // v transposed, [b][h][t]
__device__ __half g_wh[192 * CC];          // W^T hi, [n][k]
__device__ __half g_wl[192 * CC];          // W^T lo
// split-K partials; O fp16, m/l fp32 (log2 domain). 4 chunks max per qtile.
__device__ __half g_opart[512 * 128 * 64];
__device__ float g_mpart[512 * 128];
__device__ float g_lpart[512 * 128];

#define ONES_H2 0x3C003C00u   // half2(1.0, 1.0)

__device__ __forceinline__ uint32_t h2u(__half2 h) {
    union { __half2 h; uint32_t u; } cvt;
    cvt.h = h;
    return cvt.u;
}

// packed exp2: (lo, hi) fp32 -> fp16x2 -> ex2.approx.f16x2
__device__ __forceinline__ uint32_t exp2h2(float lo, float hi) {
    uint32_t d;
    asm("{\n\t.reg .b32 t;\n\t"
        "cvt.rn.f16x2.f32 t, %1, %2;\n\t"
        "ex2.approx.f16x2 %0, t;\n\t}"
        : "=r"(d) : "f"(hi), "f"(lo));
    return d;
}

__device__ __forceinline__ void mma_f16(float* d, const uint32_t* a,
                                        uint32_t b0, uint32_t b1) {
    asm volatile(
        "mma.sync.aligned.m16n8k16.row.col.f32.f16.f16.f32 "
        "{%0,%1,%2,%3}, {%4,%5,%6,%7}, {%8,%9}, {%0,%1,%2,%3};"
        : "+f"(d[0]), "+f"(d[1]), "+f"(d[2]), "+f"(d[3])
        : "r"(a[0]), "r"(a[1]), "r"(a[2]), "r"(a[3]), "r"(b0), "r"(b1));
}

__device__ __forceinline__ void ldsm4(uint32_t& r0, uint32_t& r1,
                                      uint32_t& r2, uint32_t& r3, uint32_t addr) {
    asm volatile(
        "ldmatrix.sync.aligned.m8n8.x4.shared.b16 {%0,%1,%2,%3}, [%4];"
        : "=r"(r0), "=r"(r1), "=r"(r2), "=r"(r3) : "r"(addr));
}

__device__ __forceinline__ void cp16(uint32_t dst, const void* src) {
    asm volatile("cp.async.cg.shared.global [%0], [%1], 16;"
                 :: "r"(dst), "l"(src) : "memory");
}
#define CP_COMMIT() asm volatile("cp.async.commit_group;" ::: "memory")
#define CP_WAIT1() asm volatile("cp.async.wait_group 1;" ::: "memory")
#define CP_WAIT0() asm volatile("cp.async.wait_group 0;" ::: "memory")

// ---------------------------------------------------------------------------
// W transpose + fp16 hi/lo split
// ---------------------------------------------------------------------------
__global__ __launch_bounds__(256) void wsplit_kernel(
    const float* __restrict__ Wk,
    const float* __restrict__ Wq,
    const float* __restrict__ Wv)
{
    int idx = blockIdx.x * 256 + threadIdx.x;   // 384 x 256 = 98304 = 192*512
    int k = idx / 192, n = idx - k * 192;
    const float* W = (n < 64) ? Wk : (n < 128) ? Wq : Wv;
    float w = W[k * HH + (n & 63)];
    __half hi = __float2half_rn(w);
    g_wh[n * CC + k] = hi;
    g_wl[n * CC + k] = __float2half_rn(w - __half2float(hi));
}

// ---------------------------------------------------------------------------
// Projection: fp16 2-term (xh*wh + xh*wl), m16n8k16, fp32 accum. (unchanged)
// CTA 256 thr: tile M=64 x N=192, K-chunk 32, double-buffer, grid 256.
// ---------------------------------------------------------------------------
#define PXB(buf) ((buf) * 9216)
#define PWB(buf) (18432 + (buf) * 30720)
#define PWLO 15360
#define PSMEM 79872

__global__ __launch_bounds__(256) void proj_mma(const float* __restrict__ x)
{
    extern __shared__ char smp[];
    uint32_t sbase;
    asm("{ .reg .u64 t; cvta.to.shared.u64 t, %1; cvt.u32.u64 %0, t; }"
        : "=r"(sbase) : "l"(smp));

    const int tid = threadIdx.x;
    const int w = tid >> 5;
    const int lane = tid & 31;
    const int r = lane >> 2;
    const int c = lane & 3;
    const int mw = w >> 2, nw = w & 3;
    const int row0 = blockIdx.x * 64;

    float acc[2][6][4];
#pragma unroll
    for (int mf = 0; mf < 2; mf++)
#pragma unroll
        for (int nf = 0; nf < 6; nf++)
#pragma unroll
            for (int j = 0; j < 4; j++) acc[mf][nf][j] = 0.f;

    auto issue = [&](int ck, int buf) {
        const int k0 = ck * 32;
        for (int t = tid; t < 512; t += 256) {
            int rr = t >> 3, seg = t & 7;
            cp16(sbase + PXB(buf) + rr * 144 + seg * 16,
                 &x[(size_t)(row0 + rr) * CC + k0 + seg * 4]);
        }
        for (int t = tid; t < 768; t += 256) {
            int n = t >> 2, seg = t & 3;
            cp16(sbase + PWB(buf) + n * 80 + seg * 16,
                 &g_wh[n * CC + k0 + seg * 8]);
            cp16(sbase + PWB(buf) + PWLO + n * 80 + seg * 16,
                 &g_wl[n * CC + k0 + seg * 8]);
        }
    };

    issue(0, 0);
    CP_COMMIT();

    for (int ck = 0; ck < 16; ck++) {
        const int buf = ck & 1;
        if (ck + 1 < 16) {
            issue(ck + 1, buf ^ 1);
            CP_COMMIT();
            CP_WAIT1();
        } else {
            CP_WAIT0();
        }
        __syncthreads();

        const float* Xf = (const float*)(smp + PXB(buf));
        const uint32_t* Wh32 = (const uint32_t*)(smp + PWB(buf));
        const uint32_t* Wl32 = (const uint32_t*)(smp + PWB(buf) + PWLO);

#pragma unroll
        for (int kk = 0; kk < 2; kk++) {
            uint32_t ah[2][4];
#pragma unroll
            for (int mf = 0; mf < 2; mf++) {
                int rb = 32 * mw + 16 * mf;
                const float* p0 = &Xf[(rb + r) * 36 + kk * 16 + 2 * c];
                const float* p1 = &Xf[(rb + 8 + r) * 36 + kk * 16 + 2 * c];
                float2 v0 = *(const float2*)p0;
                float2 v1 = *(const float2*)p1;
                float2 v2 = *(const float2*)(p0 + 8);
                float2 v3 = *(const float2*)(p1 + 8);
                ah[mf][0] = h2u(__floats2half2_rn(v0.x, v0.y));
                ah[mf][1] = h2u(__floats2half2_rn(v1.x, v1.y));
                ah[mf][2] = h2u(__floats2half2_rn(v2.x, v2.y));
                ah[mf][3] = h2u(__floats2half2_rn(v3.x, v3.y));
            }
#pragma unroll
            for (int nf = 0; nf < 6; nf++) {
                int bi = (48 * nw + 8 * nf + r) * 20 + kk * 8 + c;
                uint32_t bh0 = Wh32[bi], bh1 = Wh32[bi + 4];
                uint32_t bl0 = Wl32[bi], bl1 = Wl32[bi + 4];
#pragma unroll
                for (int mf = 0; mf < 2; mf++) {
                    mma_f16(acc[mf][nf], ah[mf], bh0, bh1);
                    mma_f16(acc[mf][nf], ah[mf], bl0, bl1);
                }
            }
        }
        __syncthreads();
    }

    const float qs = SCALE * LOG2E;
#pragma unroll
    for (int mf = 0; mf < 2; mf++) {
#pragma unroll
        for (int nf = 0; nf < 6; nf++) {
            int n = 48 * nw + 8 * nf + 2 * c;
            int r0 = row0 + 32 * mw + 16 * mf + r;
            float v0 = acc[mf][nf][0], v1 = acc[mf][nf][1];
            float v2 = acc[mf][nf][2], v3 = acc[mf][nf][3];
            if (n < 64) {
                *(__half2*)&g_kh[(size_t)r0 * HH + n] = __floats2half2_rn(v0, v1);
                *(__half2*)&g_kh[(size_t)(r0 + 8) * HH + n] = __floats2half2_rn(v2, v3);
            } else if (n < 128) {
                *(__half2*)&g_qh[(size_t)r0 * HH + n - 64] =
                    __floats2half2_rn(v0 * qs, v1 * qs);
                *(__half2*)&g_qh[(size_t)(r0 + 8) * HH + n - 64] =
                    __floats2half2_rn(v2 * qs, v3 * qs);
            } else {
                int hh = n - 128;
                int b = r0 >> 12, t = r0 & 4095;
                size_t vb = (size_t)b * HH * TT;
                g_vt[vb + (size_t)hh * TT + t]       = __float2half_rn(v0);
                g_vt[vb + (size_t)(hh + 1) * TT + t] = __float2half_rn(v1);
                g_vt[vb + (size_t)hh * TT + t + 8]       = __float2half_rn(v2);
                g_vt[vb + (size_t)(hh + 1) * TT + t + 8] = __float2half_rn(v3);
            }
        }
    }
}

// ---------------------------------------------------------------------------
// Split-K flash attention partial — software-pipelined:
//   softmax(kt) -> [wait/sync/prefetch kt+2] -> S-MMA(kt+1) -> PV(kt)
// 3-stage K/V buffers; chunk = up to 16 k-tiles; heavy q-tiles first.
// CTA = 256 thr (8 warps), Q tile 128 rows; warp w owns rows 16w..16w+15.
// smem: Q 18432 + K 3x9216 + V 3x9216 = 73728 B.
// ---------------------------------------------------------------------------
#define QB 0
#define KB 18432
#define KBUF 9216
#define VB 46080
#define ATTN_SMEM 73728

__global__ __launch_bounds__(256) void attn_partial()
{
    const int ch = blockIdx.x;
    const int qt = 31 - (int)blockIdx.y;     // heavy tiles first
    const int b = blockIdx.z;
    const int nkt = 2 * qt + 2;
    if (ch * CH >= nkt) return;

    extern __shared__ __half sma[];
    uint32_t sbase;
    asm("{ .reg .u64 t; cvta.to.shared.u64 t, %1; cvt.u32.u64 %0, t; }"
        : "=r"(sbase) : "l"(sma));

    const int tid = threadIdx.x;
    const int w = tid >> 5;
    const int lane = tid & 31;
    const int r = lane >> 2;
    const int c = lane & 3;
    const int rowA = 16 * w + r;
    const int q0 = qt * 128;
    const size_t base = (size_t)b * TT * HH;
    const size_t vbase = (size_t)b * HH * TT;
    const int unit = (b * 32 + qt) * 4 + ch;

    const uint32_t qa_lane = sbase + QB
        + (16 * w + (lane & 7) + ((lane >> 3) & 1) * 8) * 144
        + ((lane >> 4) & 1) * 16;
    const uint32_t b_lane =
        ((lane & 7) + ((lane >> 4) & 1) * 8) * 144 + ((lane >> 3) & 1) * 16;

    for (int i = tid; i < 128 * 8; i += 256) {
        int row = i >> 3, seg = i & 7;
        *(uint4*)((char*)sma + QB + row * 144 + seg * 16) =
            *(const uint4*)&g_qh[base + (size_t)(q0 + row) * HH + seg * 8];
    }

    const int kt_start = ch * CH;
    const int kt_end = min(kt_start + CH, nkt);

    auto issue = [&](int kt, int bi) {
        const int k0 = kt * 64;
        for (int i = tid; i < 512; i += 256) {
            int row = i >> 3, seg = i & 7;
            cp16(sbase + KB + bi * KBUF + row * 144 + seg * 16,
                 &g_kh[base + (size_t)(k0 + row) * HH + seg * 8]);
            cp16(sbase + VB + bi * KBUF + row * 144 + seg * 16,
                 &g_vt[vbase + (size_t)row * TT + k0 + seg * 8]);
        }
    };

    // S = Q K^T for one tile into s (log2-domain logits)
    auto computeS = [&](float (*s)[4], int bi) {
        const uint32_t kbuf = sbase + KB + (uint32_t)bi * KBUF;
#pragma unroll
        for (int nf = 0; nf < 8; nf++)
#pragma unroll
            for (int j = 0; j < 4; j++) s[nf][j] = 0.f;
#pragma unroll
        for (int kk = 0; kk < 4; kk++) {
            uint32_t a[4];
            ldsm4(a[0], a[1], a[2], a[3], qa_lane + kk * 32);
#pragma unroll
            for (int nfp = 0; nfp < 4; nfp++) {
                uint32_t b0, b1, b2, b3;
                ldsm4(b0, b1, b2, b3,
                      kbuf + b_lane + (uint32_t)(nfp * 2304 + kk * 32));
                mma_f16(s[2 * nfp], a, b0, b1);
                mma_f16(s[2 * nfp + 1], a, b2, b3);
            }
        }
    };

    // prologue: load first two tiles, compute S for the first
    issue(kt_start, 0);
    CP_COMMIT();
    if (kt_start + 1 < kt_end) {
        issue(kt_start + 1, 1);
        CP_COMMIT();
        CP_WAIT1();
    } else {
        CP_WAIT0();
    }
    __syncthreads();

    float s[8][4];
    computeS(s, 0);

    float mA = -1e30f, mB = -1e30f, lA = 0.f, lB = 0.f;
    float o[8][4];
#pragma unroll
    for (int nf = 0; nf < 8; nf++)
#pragma unroll
        for (int j = 0; j < 4; j++) o[nf][j] = 0.f;

    for (int kt = kt_start; kt < kt_end; kt++) {
        const int cur = (kt - kt_start) % 3;

        // causal mask (only last two k-tiles of this q-tile's range)
        if (kt >= nkt - 2) {
            int gA = q0 + rowA;
            int k0 = kt * 64;
#pragma unroll
            for (int nf = 0; nf < 8; nf++) {
                int col = k0 + nf * 8 + 2 * c;
                if (col > gA)     s[nf][0] = -1e30f;
                if (col + 1 > gA) s[nf][1] = -1e30f;
                if (col > gA + 8)     s[nf][2] = -1e30f;
                if (col + 1 > gA + 8) s[nf][3] = -1e30f;
            }
        }

        // row max (rows rowA / rowA+8); reduce over 4 c-lanes
        float xA = -1e30f, xB = -1e30f;
#pragma unroll
        for (int nf = 0; nf < 8; nf++) {
            xA = fmaxf(xA, fmaxf(s[nf][0], s[nf][1]));
            xB = fmaxf(xB, fmaxf(s[nf][2], s[nf][3]));
        }
#pragma unroll
        for (int d = 1; d < 4; d <<= 1) {
            xA = fmaxf(xA, __shfl_xor_sync(0xffffffffu, xA, d));
            xB = fmaxf(xB, __shfl_xor_sync(0xffffffffu, xB, d));
        }
        float mnA = fmaxf(mA, xA), mnB = fmaxf(mB, xB);
        float aA = exp2f(mA - mnA), aB = exp2f(mB - mnB);

        // packed fp16 exp2 -> P fragments; s dead afterwards
        uint32_t pp[8][2];
#pragma unroll
        for (int nf = 0; nf < 8; nf++) {
            pp[nf][0] = exp2h2(s[nf][0] - mnA, s[nf][1] - mnA);
            pp[nf][1] = exp2h2(s[nf][2] - mnB, s[nf][3] - mnB);
        }
        mA = mnA;
        mB = mnB;
#pragma unroll
        for (int nf = 0; nf < 8; nf++) {
            o[nf][0] *= aA; o[nf][1] *= aA;
            o[nf][2] *= aB; o[nf][3] *= aB;
        }

        // pipeline: ensure kt+1 loaded, prefetch kt+2, S-MMA(kt+1) into s
        const bool have_next = (kt + 1 < kt_end);
        if (have_next) {
            CP_WAIT0();
            __syncthreads();   // all warps done PV(kt-1); K/V[kt+1] visible
            if (kt + 2 < kt_end) {
                issue(kt + 2, (kt + 2 - kt_start) % 3);
                CP_COMMIT();
            }
            computeS(s, (kt + 1 - kt_start) % 3);
        }

        // O += P V (tile kt); row-sum l via ones-MMA
        const uint32_t vbuf = sbase + VB + (uint32_t)cur * KBUF;
        float sl[4] = {0.f, 0.f, 0.f, 0.f};
#pragma unroll
        for (int kk = 0; kk < 4; kk++) {
            uint32_t a[4] = { pp[2 * kk][0], pp[2 * kk][1],
                              pp[2 * kk + 1][0], pp[2 * kk + 1][1] };
            mma_f16(sl, a, ONES_H2, ONES_H2);
#pragma unroll
            for (int nfp = 0; nfp < 4; nfp++) {
                uint32_t b0, b1, b2, b3;
                ldsm4(b0, b1, b2, b3,
                      vbuf + b_lane + (uint32_t)(nfp * 2304 + kk * 32));
                mma_f16(o[2 * nfp], a, b0, b1);
                mma_f16(o[2 * nfp + 1], a, b2, b3);
            }
        }
        lA = lA * aA + sl[0];
        lB = lB * aB + sl[2];
    }

    // write partial O (unnormalized, fp16) + per-row m, l (fp32)
    __half2* op = (__half2*)g_opart;
#pragma unroll
    for (int nf = 0; nf < 8; nf++) {
        int colo = nf * 8 + 2 * c;
        op[((size_t)unit * 8192 + rowA * 64 + colo) >> 1] =
            __floats2half2_rn(o[nf][0], o[nf][1]);
        op[((size_t)unit * 8192 + (rowA + 8) * 64 + colo) >> 1] =
            __floats2half2_rn(o[nf][2], o[nf][3]);
    }
    if (c == 0) {
        g_mpart[unit * 128 + rowA] = mA;
        g_mpart[unit * 128 + rowA + 8] = mB;
        g_lpart[unit * 128 + rowA] = lA;
        g_lpart[unit * 128 + rowA + 8] = lB;
    }
}

// ---------------------------------------------------------------------------
// Combine: LSE-merge (log2 domain), MLP-batched loads of <=4 fp16 partials.
// grid (32, BB, 4): z = row quarter. 256 thr: row = rq*32 + tid>>3, 8 cols each.
// ---------------------------------------------------------------------------
__global__ __launch_bounds__(256) void attn_combine(float* __restrict__ out)
{
    const int qt = blockIdx.x, b = blockIdx.y, rq = blockIdx.z;
    const int tid = threadIdx.x;
    const int row = rq * 32 + (tid >> 3);
    const int co = (tid & 7) * 8;
    const int nch = (2 * qt + 2 + CH - 1) / CH;
    const int ubase = (b * 32 + qt) * 4;

    float mv[4], lv[4];
#pragma unroll
    for (int i = 0; i < 4; i++) {
        mv[i] = (i < nch) ? g_mpart[(ubase + i) * 128 + row] : -1e30f;
        lv[i] = (i < nch) ? g_lpart[(ubase + i) * 128 + row] : 0.f;
    }
    uint4 raws[4];
#pragma unroll
    for (int i = 0; i < 4; i++) {
        if (i < nch)
            raws[i] = *(const uint4*)
                &g_opart[(size_t)(ubase + i) * 8192 + row * 64 + co];
    }

    float M = -1e30f;
#pragma unroll
    for (int i = 0; i < 4; i++) M = fmaxf(M, mv[i]);

    float L = 0.f;
    float acc[8];
#pragma unroll
    for (int j = 0; j < 8; j++) acc[j] = 0.f;

#pragma unroll
    for (int i = 0; i < 4; i++) {
        if (i >= nch) break;
        float coef = exp2f(mv[i] - M);
        L += coef * lv[i];
        __half2 h0 = *(__half2*)&raws[i].x;
        __half2 h1 = *(__half2*)&raws[i].y;
        __half2 h2 = *(__half2*)&raws[i].z;
        __half2 h3 = *(__half2*)&raws[i].w;
        float2 f0 = __half22float2(h0), f1 = __half22float2(h1);
        float2 f2 = __half22float2(h2), f3 = __half22float2(h3);
        acc[0] += coef * f0.x; acc[1] += coef * f0.y;
        acc[2] += coef * f1.x; acc[3] += coef * f1.y;
        acc[4] += coef * f2.x; acc[5] += coef * f2.y;
        acc[6] += coef * f3.x; acc[7] += coef * f3.y;
    }

    float inv = 1.f / L;
    float* dst = &out[(size_t)b * TT * HH + (size_t)(qt * 128 + row) * HH + co];
#pragma unroll
    for (int j = 0; j < 2; j++) {
        float4 v = make_float4(acc[4 * j] * inv, acc[4 * j + 1] * inv,
                               acc[4 * j + 2] * inv, acc[4 * j + 3] * inv);
        *(float4*)&dst[4 * j] = v;
    }
}

// ---------------------------------------------------------------------------
extern "C" void kernel_launch(void* const* d_in, const int* in_sizes, int n_in,
                              void* d_out, int out_size)
{
    const float* x  = (const float*)d_in[0];
    const float* Wk = (const float*)d_in[1];
    const float* Wq = (const float*)d_in[2];
    const float* Wv = (const float*)d_in[3];
    float* out = (float*)d_out;

    cudaFuncSetAttribute(proj_mma, cudaFuncAttributeMaxDynamicSharedMemorySize, PSMEM);
    cudaFuncSetAttribute(attn_partial, cudaFuncAttributeMaxDynamicSharedMemorySize, ATTN_SMEM);

    wsplit_kernel<<<384, 256>>>(Wk, Wq, Wv);
    proj_mma<<<256, 256, PSMEM>>>(x);
    attn_partial<<<dim3(4, 32, BB), 256, ATTN_SMEM>>>();
    attn_combine<<<dim3(32, BB, 4), 256>>>(out);
}